// round 6
// baseline (speedup 1.0000x reference)
#include <cuda_runtime.h>

#define NN 100000
#define D 64

// Scratch (allocation-free rule: __device__ globals)
__device__ float g_aggF[NN * D];   // scatter_mean(x[src], dst) * cnt
__device__ float g_aggB[NN * D];   // scatter_mean(x[dst], src) * cnt
__device__ float g_h[NN * D];      // layer-1 output
__device__ int   g_degD[NN];
__device__ int   g_degS[NN];

// ---------------------------------------------------------------------------
// Zero agg buffers (and degree arrays on first call of the launch)
// ---------------------------------------------------------------------------
__global__ void zero_kernel(int zero_deg) {
    int tid = blockIdx.x * blockDim.x + threadIdx.x;
    const int total4 = NN * D / 4;
    if (tid < total4) {
        ((float4*)g_aggF)[tid] = make_float4(0.f, 0.f, 0.f, 0.f);
        ((float4*)g_aggB)[tid] = make_float4(0.f, 0.f, 0.f, 0.f);
    }
    if (zero_deg && tid < NN) { g_degD[tid] = 0; g_degS[tid] = 0; }
}

// ---------------------------------------------------------------------------
// Degree histogram (once per launch; same for both layers)
// ---------------------------------------------------------------------------
__global__ void degree_kernel(const int* __restrict__ src,
                              const int* __restrict__ dst, int E) {
    int e = blockIdx.x * blockDim.x + threadIdx.x;
    if (e < E) {
        atomicAdd(&g_degS[src[e]], 1);
        atomicAdd(&g_degD[dst[e]], 1);
    }
}

// ---------------------------------------------------------------------------
// Dual-direction edge scatter: 16 threads per edge, one float4 lane each.
//   aggF[dst] += h[src]   (forward / source_to_target)
//   aggB[src] += h[dst]   (backward / target_to_source)
// Uses sm_90+ vector reduction red.global.add.v4.f32.
// ---------------------------------------------------------------------------
__global__ void scatter_kernel(const float* __restrict__ h,
                               const int* __restrict__ src,
                               const int* __restrict__ dst, int E) {
    long long t = (long long)blockIdx.x * blockDim.x + threadIdx.x;
    int e = (int)(t >> 4);
    if (e >= E) return;
    int c = ((int)t & 15) << 2;

    int s = __ldg(src + e);
    int d = __ldg(dst + e);

    float4 vs = *(const float4*)(h + s * D + c);
    float4 vd = *(const float4*)(h + d * D + c);

    float* pF = g_aggF + d * D + c;
    float* pB = g_aggB + s * D + c;
    asm volatile("red.global.add.v4.f32 [%0], {%1,%2,%3,%4};"
                 :: "l"(pF), "f"(vs.x), "f"(vs.y), "f"(vs.z), "f"(vs.w) : "memory");
    asm volatile("red.global.add.v4.f32 [%0], {%1,%2,%3,%4};"
                 :: "l"(pB), "f"(vd.x), "f"(vd.y), "f"(vd.z), "f"(vd.w) : "memory");
}

// ---------------------------------------------------------------------------
// Fused GEMM: out = relu( x@Wr + (aggF/degD)@W1 + (aggB/degS)@W2 + b )
// Block: 256 threads, 64 rows x 64 cols, K streamed in 3 chunks of 64
// (x -> Wr, aggF -> W1, aggB -> W2), 1/deg folded into the smem tile load.
// Inner product uses packed fma.rn.f32x2 (FFMA2) for 2x fp32 rate.
// ---------------------------------------------------------------------------
__global__ __launch_bounds__(256) void gemm_kernel(
    const float* __restrict__ X,
    const float* __restrict__ Wr, const float* __restrict__ W1,
    const float* __restrict__ W2, const float* __restrict__ bias,
    float* __restrict__ out, int n)
{
    __shared__ float Wsm[D * D];          // 16 KB, [k][j]
    __shared__ float Insm[D * (D + 1)];   // padded, [row][k]

    int tid = threadIdx.x;
    int tx = tid & 15;         // output col group (4 cols)
    int ty = tid >> 4;         // output row group (4 rows)
    int rowBase = blockIdx.x * 64;

    unsigned long long acc[4][2];
#pragma unroll
    for (int r = 0; r < 4; r++) { acc[r][0] = 0ULL; acc[r][1] = 0ULL; }

    const float* ins[3] = { X, g_aggF, g_aggB };
    const float* ws[3]  = { Wr, W1, W2 };

    for (int chunk = 0; chunk < 3; chunk++) {
        __syncthreads();
        // --- load 64x64 weight chunk (coalesced float4) ---
        const float* W = ws[chunk];
#pragma unroll
        for (int i = 0; i < 4; i++) {
            int idx = tid + i * 256;                   // float4 index, 0..1023
            ((float4*)Wsm)[idx] = ((const float4*)W)[idx];
        }
        // --- load 64x64 input tile, scaling agg chunks by 1/max(deg,1) ---
        const float* In = ins[chunk];
#pragma unroll
        for (int i = 0; i < 4; i++) {
            int v = tid + i * 256;                     // 0..1023
            int row = v >> 4;
            int c4 = (v & 15) << 2;
            int grow = rowBase + row;
            float4 val = make_float4(0.f, 0.f, 0.f, 0.f);
            float sc = 1.0f;
            if (grow < n) {
                val = *(const float4*)(In + grow * D + c4);
                if (chunk == 1)      sc = 1.0f / (float)max(g_degD[grow], 1);
                else if (chunk == 2) sc = 1.0f / (float)max(g_degS[grow], 1);
            }
            float* p = &Insm[row * (D + 1) + c4];
            p[0] = val.x * sc; p[1] = val.y * sc;
            p[2] = val.z * sc; p[3] = val.w * sc;
        }
        __syncthreads();

#pragma unroll 16
        for (int k = 0; k < D; k++) {
            float4 w4 = *(const float4*)&Wsm[k * D + (tx << 2)];
            unsigned long long w01, w23;
            asm("mov.b64 %0, {%1, %2};" : "=l"(w01) : "f"(w4.x), "f"(w4.y));
            asm("mov.b64 %0, {%1, %2};" : "=l"(w23) : "f"(w4.z), "f"(w4.w));
#pragma unroll
            for (int r = 0; r < 4; r++) {
                float a = Insm[(ty * 4 + r) * (D + 1) + k];
                unsigned long long a2;
                asm("mov.b64 %0, {%1, %1};" : "=l"(a2) : "f"(a));
                asm("fma.rn.f32x2 %0, %1, %2, %0;" : "+l"(acc[r][0]) : "l"(a2), "l"(w01));
                asm("fma.rn.f32x2 %0, %1, %2, %0;" : "+l"(acc[r][1]) : "l"(a2), "l"(w23));
            }
        }
    }

    // --- epilogue: + bias, relu, store ---
    int c0 = tx << 2;
    float b0 = __ldg(bias + c0 + 0), b1 = __ldg(bias + c0 + 1);
    float b2 = __ldg(bias + c0 + 2), b3 = __ldg(bias + c0 + 3);
#pragma unroll
    for (int r = 0; r < 4; r++) {
        int grow = rowBase + ty * 4 + r;
        if (grow < n) {
            float o0, o1, o2, o3;
            asm("mov.b64 {%0, %1}, %2;" : "=f"(o0), "=f"(o1) : "l"(acc[r][0]));
            asm("mov.b64 {%0, %1}, %2;" : "=f"(o2), "=f"(o3) : "l"(acc[r][1]));
            float4 ov;
            ov.x = fmaxf(o0 + b0, 0.f);
            ov.y = fmaxf(o1 + b1, 0.f);
            ov.z = fmaxf(o2 + b2, 0.f);
            ov.w = fmaxf(o3 + b3, 0.f);
            *(float4*)(out + grow * D + c0) = ov;
        }
    }
}

// ---------------------------------------------------------------------------
extern "C" void kernel_launch(void* const* d_in, const int* in_sizes, int n_in,
                              void* d_out, int out_size) {
    const float* x    = (const float*)d_in[0];
    const int*   ei   = (const int*)d_in[1];
    const float* W1_0 = (const float*)d_in[2];
    const float* W2_0 = (const float*)d_in[3];
    const float* Wr_0 = (const float*)d_in[4];
    const float* br_0 = (const float*)d_in[5];
    const float* W1_1 = (const float*)d_in[6];
    const float* W2_1 = (const float*)d_in[7];
    const float* Wr_1 = (const float*)d_in[8];
    const float* br_1 = (const float*)d_in[9];
    float* out = (float*)d_out;

    int E = in_sizes[1] / 2;
    const int* src = ei;
    const int* dst = ei + E;
    int n = in_sizes[0] / D;

    float* hbuf = nullptr;
    cudaGetSymbolAddress((void**)&hbuf, g_h);

    const int zthreads = NN * D / 4;                 // covers NN for deg too
    const int zblocks  = (zthreads + 255) / 256;
    const int dblocks  = (E + 255) / 256;
    long long sthreads = (long long)E * 16;
    const int sblocks  = (int)((sthreads + 255) / 256);
    const int gblocks  = (n + 63) / 64;

    // ---- Layer 0 ----
    zero_kernel<<<zblocks, 256>>>(1);
    degree_kernel<<<dblocks, 256>>>(src, dst, E);
    scatter_kernel<<<sblocks, 256>>>(x, src, dst, E);
    gemm_kernel<<<gblocks, 256>>>(x, Wr_0, W1_0, W2_0, br_0, hbuf, n);

    // ---- Layer 1 ----
    zero_kernel<<<zblocks, 256>>>(0);
    scatter_kernel<<<sblocks, 256>>>(hbuf, src, dst, E);
    gemm_kernel<<<gblocks, 256>>>(hbuf, Wr_1, W1_1, W2_1, br_1, out, n);
}

// round 13
// speedup vs baseline: 1.4054x; 1.4054x over previous
#include <cuda_runtime.h>

#define NN 100000
#define D 64
#define EMAX 1250000
#define NB 391            // (NN + 255) / 256
#define ISTRIDE 68        // D + 4: rows stay 16B-aligned for LDS.128

// Scratch (allocation-free rule: __device__ globals)
__device__ float g_aggF[NN * D];     // mean over in-neighbors  (dst-indexed)
__device__ float g_aggB[NN * D];     // mean over out-neighbors (src-indexed)
__device__ float g_h[NN * D];        // layer-1 output
__device__ int   g_degD[NN], g_degS[NN];
__device__ int   g_rowD[NN + 1], g_rowS[NN + 1];
__device__ int   g_curD[NN], g_curS[NN];
__device__ int   g_adjD[EMAX], g_adjS[EMAX];
__device__ int   g_bsumD[512], g_bsumS[512], g_boffD[512], g_boffS[512];

// ---------------------------------------------------------------------------
__global__ void init_kernel() {
    int i = blockIdx.x * blockDim.x + threadIdx.x;
    if (i < NN) { g_degD[i] = 0; g_degS[i] = 0; }
}

__global__ void degree_kernel(const int* __restrict__ src,
                              const int* __restrict__ dst, int E) {
    int e = blockIdx.x * blockDim.x + threadIdx.x;
    if (e < E) {
        atomicAdd(&g_degS[src[e]], 1);
        atomicAdd(&g_degD[dst[e]], 1);
    }
}

// --- 3-kernel exclusive scan over degrees (both directions at once) --------
__global__ void scan1_kernel() {
    __shared__ int sD[256], sS[256];
    int t = threadIdx.x, i = blockIdx.x * 256 + t;
    int dD = (i < NN) ? g_degD[i] : 0;
    int dS = (i < NN) ? g_degS[i] : 0;
    sD[t] = dD; sS[t] = dS; __syncthreads();
    for (int off = 1; off < 256; off <<= 1) {
        int vD = 0, vS = 0;
        if (t >= off) { vD = sD[t - off]; vS = sS[t - off]; }
        __syncthreads();
        if (t >= off) { sD[t] += vD; sS[t] += vS; }
        __syncthreads();
    }
    if (i < NN) { g_rowD[i] = sD[t] - dD; g_rowS[i] = sS[t] - dS; }
    if (t == 255) { g_bsumD[blockIdx.x] = sD[255]; g_bsumS[blockIdx.x] = sS[255]; }
}

__global__ void scan2_kernel(int nb) {
    __shared__ int sD[512], sS[512];
    int t = threadIdx.x;
    int vD = (t < nb) ? g_bsumD[t] : 0;
    int vS = (t < nb) ? g_bsumS[t] : 0;
    sD[t] = vD; sS[t] = vS; __syncthreads();
    for (int off = 1; off < 512; off <<= 1) {
        int aD = 0, aS = 0;
        if (t >= off) { aD = sD[t - off]; aS = sS[t - off]; }
        __syncthreads();
        if (t >= off) { sD[t] += aD; sS[t] += aS; }
        __syncthreads();
    }
    if (t < nb) { g_boffD[t] = sD[t] - vD; g_boffS[t] = sS[t] - vS; }
}

__global__ void scan3_kernel(int E) {
    int t = threadIdx.x, i = blockIdx.x * 256 + t;
    if (i < NN) {
        int rD = g_rowD[i] + g_boffD[blockIdx.x];
        int rS = g_rowS[i] + g_boffS[blockIdx.x];
        g_rowD[i] = rD; g_rowS[i] = rS;
        g_curD[i] = rD; g_curS[i] = rS;
    }
    if (i == 0) { g_rowD[NN] = E; g_rowS[NN] = E; }
}

__global__ void fill_kernel(const int* __restrict__ src,
                            const int* __restrict__ dst, int E) {
    int e = blockIdx.x * blockDim.x + threadIdx.x;
    if (e < E) {
        int s = src[e], d = dst[e];
        int pD = atomicAdd(&g_curD[d], 1); g_adjD[pD] = s;
        int pS = atomicAdd(&g_curS[s], 1); g_adjS[pS] = d;
    }
}

// ---------------------------------------------------------------------------
// CSR gather-mean: half-warp (16 lanes) per node, float4 per lane.
// out[v] = mean_{u in adj[row[v]:row[v+1]]} h[u]   (zero if no neighbors)
// 4-way neighbor unroll for memory-level parallelism.
// ---------------------------------------------------------------------------
__global__ void gather_kernel(const float* __restrict__ h,
                              const int* __restrict__ rowptr,
                              const int* __restrict__ adj,
                              float* __restrict__ out) {
    int tid = blockIdx.x * blockDim.x + threadIdx.x;
    int v = tid >> 4;
    if (v >= NN) return;
    int c = (tid & 15) << 2;

    int p0 = __ldg(rowptr + v), p1 = __ldg(rowptr + v + 1);
    float4 acc = make_float4(0.f, 0.f, 0.f, 0.f);
    int j = p0;
    for (; j + 4 <= p1; j += 4) {
        int u0 = __ldg(adj + j),     u1 = __ldg(adj + j + 1);
        int u2 = __ldg(adj + j + 2), u3 = __ldg(adj + j + 3);
        float4 a = *(const float4*)(h + u0 * D + c);
        float4 b = *(const float4*)(h + u1 * D + c);
        float4 e = *(const float4*)(h + u2 * D + c);
        float4 f = *(const float4*)(h + u3 * D + c);
        acc.x += (a.x + b.x) + (e.x + f.x);
        acc.y += (a.y + b.y) + (e.y + f.y);
        acc.z += (a.z + b.z) + (e.z + f.z);
        acc.w += (a.w + b.w) + (e.w + f.w);
    }
    for (; j < p1; j++) {
        int u = __ldg(adj + j);
        float4 a = *(const float4*)(h + u * D + c);
        acc.x += a.x; acc.y += a.y; acc.z += a.z; acc.w += a.w;
    }
    float inv = (p1 > p0) ? 1.0f / (float)(p1 - p0) : 0.f;
    acc.x *= inv; acc.y *= inv; acc.z *= inv; acc.w *= inv;
    *(float4*)(out + v * D + c) = acc;
}

// ---------------------------------------------------------------------------
// Fused GEMM: out = relu( x@Wr + aggF@W1 + aggB@W2 + b )   (agg already means)
// K stepped by 4, LDS.128 for both operands, FFMA2 inner product.
// ---------------------------------------------------------------------------
__global__ __launch_bounds__(256) void gemm_kernel(
    const float* __restrict__ X,
    const float* __restrict__ Wr, const float* __restrict__ W1,
    const float* __restrict__ W2, const float* __restrict__ bias,
    float* __restrict__ out, int n)
{
    __shared__ float Wsm[D * D];
    __shared__ float Insm[D * ISTRIDE];

    int tid = threadIdx.x;
    int tx = tid & 15;
    int ty = tid >> 4;
    int rowBase = blockIdx.x * 64;

    unsigned long long acc[4][2];
#pragma unroll
    for (int r = 0; r < 4; r++) { acc[r][0] = 0ULL; acc[r][1] = 0ULL; }

    const float* ins[3] = { X, g_aggF, g_aggB };
    const float* ws[3]  = { Wr, W1, W2 };

    for (int chunk = 0; chunk < 3; chunk++) {
        __syncthreads();
        const float* W = ws[chunk];
#pragma unroll
        for (int i = 0; i < 4; i++) {
            int idx = tid + i * 256;
            ((float4*)Wsm)[idx] = ((const float4*)W)[idx];
        }
        const float* In = ins[chunk];
#pragma unroll
        for (int i = 0; i < 4; i++) {
            int v = tid + i * 256;
            int row = v >> 4;
            int c4 = (v & 15) << 2;
            int grow = rowBase + row;
            float4 val = make_float4(0.f, 0.f, 0.f, 0.f);
            if (grow < n) val = *(const float4*)(In + grow * D + c4);
            *(float4*)&Insm[row * ISTRIDE + c4] = val;
        }
        __syncthreads();

#pragma unroll 4
        for (int k = 0; k < D; k += 4) {
            unsigned long long w01[4], w23[4];
#pragma unroll
            for (int i = 0; i < 4; i++) {
                float4 w4 = *(const float4*)&Wsm[(k + i) * D + (tx << 2)];
                asm("mov.b64 %0, {%1, %2};" : "=l"(w01[i]) : "f"(w4.x), "f"(w4.y));
                asm("mov.b64 %0, {%1, %2};" : "=l"(w23[i]) : "f"(w4.z), "f"(w4.w));
            }
#pragma unroll
            for (int r = 0; r < 4; r++) {
                float4 a4 = *(const float4*)&Insm[(ty * 4 + r) * ISTRIDE + k];
                unsigned long long a2;
                asm("mov.b64 %0, {%1, %1};" : "=l"(a2) : "f"(a4.x));
                asm("fma.rn.f32x2 %0, %1, %2, %0;" : "+l"(acc[r][0]) : "l"(a2), "l"(w01[0]));
                asm("fma.rn.f32x2 %0, %1, %2, %0;" : "+l"(acc[r][1]) : "l"(a2), "l"(w23[0]));
                asm("mov.b64 %0, {%1, %1};" : "=l"(a2) : "f"(a4.y));
                asm("fma.rn.f32x2 %0, %1, %2, %0;" : "+l"(acc[r][0]) : "l"(a2), "l"(w01[1]));
                asm("fma.rn.f32x2 %0, %1, %2, %0;" : "+l"(acc[r][1]) : "l"(a2), "l"(w23[1]));
                asm("mov.b64 %0, {%1, %1};" : "=l"(a2) : "f"(a4.z));
                asm("fma.rn.f32x2 %0, %1, %2, %0;" : "+l"(acc[r][0]) : "l"(a2), "l"(w01[2]));
                asm("fma.rn.f32x2 %0, %1, %2, %0;" : "+l"(acc[r][1]) : "l"(a2), "l"(w23[2]));
                asm("mov.b64 %0, {%1, %1};" : "=l"(a2) : "f"(a4.w));
                asm("fma.rn.f32x2 %0, %1, %2, %0;" : "+l"(acc[r][0]) : "l"(a2), "l"(w01[3]));
                asm("fma.rn.f32x2 %0, %1, %2, %0;" : "+l"(acc[r][1]) : "l"(a2), "l"(w23[3]));
            }
        }
    }

    int c0 = tx << 2;
    float b0 = __ldg(bias + c0 + 0), b1 = __ldg(bias + c0 + 1);
    float b2 = __ldg(bias + c0 + 2), b3 = __ldg(bias + c0 + 3);
#pragma unroll
    for (int r = 0; r < 4; r++) {
        int grow = rowBase + ty * 4 + r;
        if (grow < n) {
            float o0, o1, o2, o3;
            asm("mov.b64 {%0, %1}, %2;" : "=f"(o0), "=f"(o1) : "l"(acc[r][0]));
            asm("mov.b64 {%0, %1}, %2;" : "=f"(o2), "=f"(o3) : "l"(acc[r][1]));
            float4 ov;
            ov.x = fmaxf(o0 + b0, 0.f);
            ov.y = fmaxf(o1 + b1, 0.f);
            ov.z = fmaxf(o2 + b2, 0.f);
            ov.w = fmaxf(o3 + b3, 0.f);
            *(float4*)(out + grow * D + c0) = ov;
        }
    }
}

// ---------------------------------------------------------------------------
extern "C" void kernel_launch(void* const* d_in, const int* in_sizes, int n_in,
                              void* d_out, int out_size) {
    const float* x    = (const float*)d_in[0];
    const int*   ei   = (const int*)d_in[1];
    const float* W1_0 = (const float*)d_in[2];
    const float* W2_0 = (const float*)d_in[3];
    const float* Wr_0 = (const float*)d_in[4];
    const float* br_0 = (const float*)d_in[5];
    const float* W1_1 = (const float*)d_in[6];
    const float* W2_1 = (const float*)d_in[7];
    const float* Wr_1 = (const float*)d_in[8];
    const float* br_1 = (const float*)d_in[9];
    float* out = (float*)d_out;

    int E = in_sizes[1] / 2;
    const int* src = ei;
    const int* dst = ei + E;
    int n = in_sizes[0] / D;

    float* hbuf = nullptr;
    cudaGetSymbolAddress((void**)&hbuf, g_h);

    float* aggF = nullptr; float* aggB = nullptr;
    cudaGetSymbolAddress((void**)&aggF, g_aggF);
    cudaGetSymbolAddress((void**)&aggB, g_aggB);
    int* rowD = nullptr; int* rowS = nullptr; int* adjD = nullptr; int* adjS = nullptr;
    cudaGetSymbolAddress((void**)&rowD, g_rowD);
    cudaGetSymbolAddress((void**)&rowS, g_rowS);
    cudaGetSymbolAddress((void**)&adjD, g_adjD);
    cudaGetSymbolAddress((void**)&adjS, g_adjS);

    const int eblocks = (E + 255) / 256;
    const int gthreads = NN * 16;
    const int gablocks = (gthreads + 255) / 256;
    const int gemmblocks = (n + 63) / 64;

    // ---- Build CSR (both directions) once; reused by both layers ----
    init_kernel<<<NB, 256>>>();
    degree_kernel<<<eblocks, 256>>>(src, dst, E);
    scan1_kernel<<<NB, 256>>>();
    scan2_kernel<<<1, 512>>>(NB);
    scan3_kernel<<<NB, 256>>>(E);
    fill_kernel<<<eblocks, 256>>>(src, dst, E);

    // ---- Layer 0 ----
    gather_kernel<<<gablocks, 256>>>(x, rowD, adjD, aggF);
    gather_kernel<<<gablocks, 256>>>(x, rowS, adjS, aggB);
    gemm_kernel<<<gemmblocks, 256>>>(x, Wr_0, W1_0, W2_0, br_0, hbuf, n);

    // ---- Layer 1 ----
    gather_kernel<<<gablocks, 256>>>(hbuf, rowD, adjD, aggF);
    gather_kernel<<<gablocks, 256>>>(hbuf, rowS, adjS, aggB);
    gemm_kernel<<<gemmblocks, 256>>>(hbuf, Wr_1, W1_1, W2_1, br_1, out, n);
}